// round 15
// baseline (speedup 1.0000x reference)
#include <cuda_runtime.h>
#include <cuda_fp16.h>
#include <math.h>
#include <stdint.h>

#define NB 16
#define NL 512
#define ND 512
#define NCB 4096
#define NTOT (NB*NL*ND)

// ---------------- scratch (device globals, allocation-free) ----------------
__device__ float g_resid[NTOT];
__device__ float g_tapw[12 * NCB * ND];          // [(p*3+tap)][code][o]
__device__ unsigned long long g_keys[NB*NL];
__device__ unsigned g_cand[NB*NL*64];
__device__ float g_esq[NCB];
__device__ float g_part[NB*32*ND];
__device__ __half g_embH[NCB*ND], g_embL[NCB*ND];
__device__ __half g_zH[NB*NL*ND], g_zL[NB*NL*ND];
__device__ __half g_wtH[4*3*ND*ND], g_wtL[4*3*ND*ND];  // [p][tap][o][i]

__device__ __forceinline__ void split_h(float x, __half& h, __half& l) {
    h = __float2half_rn(x);
    l = __float2half_rn(x - __half2float(h));
}

// ---------------- setup ----------------
__global__ void k_setup_esq(const float* __restrict__ embed) {
    int gw = (blockIdx.x * blockDim.x + threadIdx.x) >> 5;
    int lane = threadIdx.x & 31;
    if (gw >= NCB) return;
    const float* e = embed + gw * ND;
    float s = 0.f;
    for (int d = lane; d < ND; d += 32) { float v = e[d]; s = fmaf(v, v, s); }
    for (int o = 16; o > 0; o >>= 1) s += __shfl_xor_sync(0xffffffffu, s, o);
    if (lane == 0) g_esq[gw] = s;
}
__global__ void k_split_emb(const float* __restrict__ embed) {
    for (int t = blockIdx.x * blockDim.x + threadIdx.x; t < NCB * ND;
         t += gridDim.x * blockDim.x)
        split_h(embed[t], g_embH[t], g_embL[t]);
}
// split weights for ONE phi p
__global__ void k_setup_wt(const float* __restrict__ phi_w, int p) {
    int total = 3 * ND * ND;
    for (int t = blockIdx.x * blockDim.x + threadIdx.x; t < total;
         t += gridDim.x * blockDim.x) {
        int i = t & 511;
        int q = t >> 9;
        int o = q & 511;
        int tap = q >> 9;
        int g = p * (3 * ND * ND) + t;
        split_h(phi_w[((p * ND + o) * ND + i) * 3 + tap], g_wtH[g], g_wtL[g]);
    }
}

// ---------------- downsample (block mean) + split ----------------
__global__ void k_down(int s, const float* __restrict__ src0) {   // r <= 16
    int r = NL / s;
    float inv = 1.0f / (float)r;
    int total = NB * s * ND;
    for (int t = blockIdx.x * blockDim.x + threadIdx.x; t < total;
         t += gridDim.x * blockDim.x) {
        int d = t & 511;
        int bt = t >> 9;
        int b = bt / s, tt = bt % s;
        const float* src = src0 + (b * NL + tt * r) * ND + d;
        float acc = 0.f;
        for (int j = 0; j < r; j++) acc += src[j * ND];
        acc *= inv;
        split_h(acc, g_zH[t], g_zL[t]);
    }
}
__global__ void k_down1(int s, int segs, const float* __restrict__ src0) {
    float4* part = (float4*)g_part;
    int total = NB * s * segs * 128;
    for (int t = blockIdx.x * blockDim.x + threadIdx.x; t < total;
         t += gridDim.x * blockDim.x) {
        int d4 = t & 127;
        int rem = t >> 7;
        int seg = rem % segs;
        int bt = rem / segs;
        int b = bt / s, tt = bt % s;
        int r = NL / s;
        const float4* src = (const float4*)(src0 + (b * NL + tt * r + seg * 16) * ND) + d4;
        float4 a = make_float4(0.f, 0.f, 0.f, 0.f);
        for (int j = 0; j < 16; j++) {
            float4 v = src[j * 128];
            a.x += v.x; a.y += v.y; a.z += v.z; a.w += v.w;
        }
        part[(bt * segs + seg) * 128 + d4] = a;
    }
}
__global__ void k_down2(int s, int segs) {
    const float4* part = (const float4*)g_part;
    float inv = (float)s * (1.0f / (float)NL);
    int total = NB * s * 128;
    for (int t = blockIdx.x * blockDim.x + threadIdx.x; t < total;
         t += gridDim.x * blockDim.x) {
        int d4 = t & 127;
        int bt = t >> 7;
        float4 a = make_float4(0.f, 0.f, 0.f, 0.f);
        for (int sg = 0; sg < segs; sg++) {
            float4 v = part[(bt * segs + sg) * 128 + d4];
            a.x += v.x; a.y += v.y; a.z += v.z; a.w += v.w;
        }
        int base = (bt << 9) + (d4 << 2);
        split_h(a.x * inv, g_zH[base + 0], g_zL[base + 0]);
        split_h(a.y * inv, g_zH[base + 1], g_zL[base + 1]);
        split_h(a.z * inv, g_zH[base + 2], g_zL[base + 2]);
        split_h(a.w * inv, g_zH[base + 3], g_zL[base + 3]);
    }
}

// ---------------- mma helpers ----------------
#define MMA16816(d, a, b0, b1) \
    asm volatile("mma.sync.aligned.m16n8k16.row.col.f32.f16.f16.f32 " \
        "{%0,%1,%2,%3}, {%4,%5,%6,%7}, {%8,%9}, {%0,%1,%2,%3};" \
        : "+f"((d)[0]), "+f"((d)[1]), "+f"((d)[2]), "+f"((d)[3]) \
        : "r"((a)[0]), "r"((a)[1]), "r"((a)[2]), "r"((a)[3]), "r"(b0), "r"(b1))
__device__ __forceinline__ uint32_t smem_u32(const void* p) {
    uint32_t a;
    asm("{ .reg .u64 t; cvta.to.shared.u64 t, %1; cvt.u32.u64 %0, t; }" : "=r"(a) : "l"(p));
    return a;
}
__device__ __forceinline__ void cp16(uint32_t s, const void* g, int sz) {
    asm volatile("cp.async.cg.shared.global [%0], [%1], 16, %2;"
        :: "r"(s), "l"(g), "r"(sz) : "memory");
}
#define CP_COMMIT() asm volatile("cp.async.commit_group;" ::: "memory")
#define CP_WAIT1()  asm volatile("cp.async.wait_group 1;" ::: "memory")
#define CP_WAIT0()  asm volatile("cp.async.wait_group 0;" ::: "memory")
__device__ __forceinline__ void ldsm4(uint32_t* r, uint32_t addr) {
    asm volatile("ldmatrix.sync.aligned.m8n8.x4.shared.b16 {%0,%1,%2,%3}, [%4];"
        : "=r"(r[0]), "=r"(r[1]), "=r"(r[2]), "=r"(r[3]) : "r"(addr));
}
#define PITCH_B 80

// ---------------- precompute: tapw = embed @ W_tap^T (3-term fp16), per-phi ---
#define STAGE3_B 40960
__global__ __launch_bounds__(256, 2) void k_gemm_pre(int p) {
    extern __shared__ __align__(16) char dsm[];
    uint32_t sbase = smem_u32(dsm);
    int tid = threadIdx.x;
    int lane = tid & 31, wid = tid >> 5;
    int wm = wid >> 2, wn = wid & 3;
    int gr4 = lane >> 2, gc4 = lane & 3;
    int m0 = blockIdx.x * 128, n0 = blockIdx.y * 128;
    int z = p * 3 + blockIdx.z;   // (phi, tap)

    const __half* BH = g_wtH + (size_t)z * (ND * ND);
    const __half* BL = g_wtL + (size_t)z * (ND * ND);

    int lrow = tid >> 1;
    size_t aoff = (size_t)(m0 + lrow) * ND;
    size_t boff = (size_t)(n0 + lrow) * ND;
    int cByte = (tid & 1) * 32;
    const char* gAh = (const char*)(g_embH + aoff) + cByte;
    const char* gAl = (const char*)(g_embL + aoff) + cByte;
    const char* gBh = (const char*)(BH     + boff) + cByte;
    const char* gBl = (const char*)(BL     + boff) + cByte;
    uint32_t sOff = sbase + lrow * PITCH_B + cByte;

    int lm = lane & 15, lk = lane >> 4;
    uint32_t aFrag = sbase + (wm * 64 + lm) * PITCH_B + lk * 16;
    uint32_t bFrag = sbase + 20480 + (wn * 32 + lm) * PITCH_B + lk * 16;

    float acc[4][4][4];
#pragma unroll
    for (int i = 0; i < 4; i++)
#pragma unroll
        for (int j = 0; j < 4; j++)
#pragma unroll
            for (int q = 0; q < 4; q++) acc[i][j][q] = 0.f;

#define ISSUE3(stg, kb) do { \
        uint32_t so = sOff + (stg) * STAGE3_B; \
        int gb = (kb) * 64; \
        cp16(so,              gAh + gb,      16); \
        cp16(so + 16,         gAh + gb + 16, 16); \
        cp16(so + 10240,      gAl + gb,      16); \
        cp16(so + 10240 + 16, gAl + gb + 16, 16); \
        cp16(so + 20480,      gBh + gb,      16); \
        cp16(so + 20480 + 16, gBh + gb + 16, 16); \
        cp16(so + 30720,      gBl + gb,      16); \
        cp16(so + 30720 + 16, gBl + gb + 16, 16); \
        CP_COMMIT(); \
    } while (0)

    ISSUE3(0, 0);
    for (int kb = 0; kb < 16; kb++) {
        int st = kb & 1;
        __syncthreads();
        if (kb + 1 < 16) { ISSUE3((kb + 1) & 1, kb + 1); CP_WAIT1(); }
        else             { CP_WAIT0(); }
        __syncthreads();
        uint32_t sa = (uint32_t)st * STAGE3_B;
#pragma unroll
        for (int kp = 0; kp < 2; kp++) {
            uint32_t ah[4][4], al[4][4];
#pragma unroll
            for (int mt = 0; mt < 4; mt++) {
                uint32_t adr = aFrag + sa + mt * (16 * PITCH_B) + kp * 32;
                ldsm4(ah[mt], adr);
                ldsm4(al[mt], adr + 10240);
            }
#pragma unroll
            for (int ntp = 0; ntp < 2; ntp++) {
                uint32_t bh[4], bl[4];
                uint32_t badr = bFrag + sa + ntp * (16 * PITCH_B) + kp * 32;
                ldsm4(bh, badr);
                ldsm4(bl, badr + 10240);
#pragma unroll
                for (int mt = 0; mt < 4; mt++) {
                    MMA16816(acc[mt][2 * ntp],     ah[mt], bh[0], bh[2]);
                    MMA16816(acc[mt][2 * ntp],     al[mt], bh[0], bh[2]);
                    MMA16816(acc[mt][2 * ntp],     ah[mt], bl[0], bl[2]);
                    MMA16816(acc[mt][2 * ntp + 1], ah[mt], bh[1], bh[3]);
                    MMA16816(acc[mt][2 * ntp + 1], al[mt], bh[1], bh[3]);
                    MMA16816(acc[mt][2 * ntp + 1], ah[mt], bl[1], bl[3]);
                }
            }
        }
    }
#undef ISSUE3

    float* outz = g_tapw + (size_t)z * (NCB * ND);
#pragma unroll
    for (int mt = 0; mt < 4; mt++) {
#pragma unroll
        for (int h = 0; h < 2; h++) {
            int m = m0 + wm * 64 + mt * 16 + gr4 + 8 * h;
            float* crow = outz + ((size_t)m << 9);
#pragma unroll
            for (int nt = 0; nt < 4; nt++) {
                int c = n0 + wn * 32 + nt * 8 + 2 * gc4;
                *(float2*)(crow + c) =
                    make_float2(acc[mt][nt][2 * h], acc[mt][nt][2 * h + 1]);
            }
        }
    }
}

// ---------------- quantize: 1-term hi*hi GEMM + per-block top-2 candidates ----
#define STAGE1_B 20480
__global__ __launch_bounds__(256, 2) void k_quant1(int nTok) {
    extern __shared__ __align__(16) char dsm[];
    __shared__ unsigned long long smerge[128 * 8];
    uint32_t sbase = smem_u32(dsm);
    int tid = threadIdx.x;
    int lane = tid & 31, wid = tid >> 5;
    int wm = wid >> 2, wn = wid & 3;
    int gr4 = lane >> 2, gc4 = lane & 3;
    int m0 = blockIdx.x * 128, n0 = blockIdx.y * 128;

    int lrow = tid >> 1;
    int gm = m0 + lrow;
    int asz = (gm < nTok) ? 16 : 0;
    size_t aoff = (size_t)(gm < nTok ? gm : 0) * ND;
    size_t boff = (size_t)(n0 + lrow) * ND;
    int cByte = (tid & 1) * 32;
    const char* gAh = (const char*)(g_zH   + aoff) + cByte;
    const char* gBh = (const char*)(g_embH + boff) + cByte;
    uint32_t sOff = sbase + lrow * PITCH_B + cByte;

    int lm = lane & 15, lk = lane >> 4;
    uint32_t aFrag = sbase + (wm * 64 + lm) * PITCH_B + lk * 16;
    uint32_t bFrag = sbase + 10240 + (wn * 32 + lm) * PITCH_B + lk * 16;

    float acc[4][4][4];
#pragma unroll
    for (int i = 0; i < 4; i++)
#pragma unroll
        for (int j = 0; j < 4; j++)
#pragma unroll
            for (int q = 0; q < 4; q++) acc[i][j][q] = 0.f;

#define ISSUE1(stg, kb) do { \
        uint32_t so = sOff + (stg) * STAGE1_B; \
        int gb = (kb) * 64; \
        cp16(so,              gAh + gb,      asz); \
        cp16(so + 16,         gAh + gb + 16, asz); \
        cp16(so + 10240,      gBh + gb,      16); \
        cp16(so + 10240 + 16, gBh + gb + 16, 16); \
        CP_COMMIT(); \
    } while (0)

    ISSUE1(0, 0);
    for (int kb = 0; kb < 16; kb++) {
        int st = kb & 1;
        __syncthreads();
        if (kb + 1 < 16) { ISSUE1((kb + 1) & 1, kb + 1); CP_WAIT1(); }
        else             { CP_WAIT0(); }
        __syncthreads();
        uint32_t sa = (uint32_t)st * STAGE1_B;
#pragma unroll
        for (int kp = 0; kp < 2; kp++) {
            uint32_t ah[4][4];
#pragma unroll
            for (int mt = 0; mt < 4; mt++)
                ldsm4(ah[mt], aFrag + sa + mt * (16 * PITCH_B) + kp * 32);
#pragma unroll
            for (int ntp = 0; ntp < 2; ntp++) {
                uint32_t bh[4];
                ldsm4(bh, bFrag + sa + ntp * (16 * PITCH_B) + kp * 32);
#pragma unroll
                for (int mt = 0; mt < 4; mt++) {
                    MMA16816(acc[mt][2 * ntp],     ah[mt], bh[0], bh[2]);
                    MMA16816(acc[mt][2 * ntp + 1], ah[mt], bh[1], bh[3]);
                }
            }
        }
    }
#undef ISSUE1

#pragma unroll
    for (int mt = 0; mt < 4; mt++) {
#pragma unroll
        for (int h = 0; h < 2; h++) {
            int row = wm * 64 + mt * 16 + gr4 + 8 * h;
            unsigned long long k1 = 0xFFFFFFFFFFFFFFFFULL, k2 = k1;
#pragma unroll
            for (int nt = 0; nt < 4; nt++) {
#pragma unroll
                for (int e = 0; e < 2; e++) {
                    int c = n0 + wn * 32 + nt * 8 + 2 * gc4 + e;
                    float sc = fmaf(-2.f, acc[mt][nt][2 * h + e], __ldg(&g_esq[c]));
                    unsigned u = __float_as_uint(sc);
                    u = (u & 0x80000000u) ? ~u : (u | 0x80000000u);
                    unsigned long long key = ((unsigned long long)u << 32) | (unsigned)c;
                    if (key < k1) { k2 = k1; k1 = key; }
                    else if (key < k2) { k2 = key; }
                }
            }
#pragma unroll
            for (int o = 1; o <= 2; o <<= 1) {
                unsigned long long o1 = __shfl_xor_sync(0xffffffffu, k1, o);
                unsigned long long o2 = __shfl_xor_sync(0xffffffffu, k2, o);
                unsigned long long lo = (k1 < o1) ? k1 : o1;
                unsigned long long hi = (k1 < o1) ? o1 : k1;
                unsigned long long mn2 = (k2 < o2) ? k2 : o2;
                k1 = lo;
                k2 = (hi < mn2) ? hi : mn2;
            }
            if (gc4 == 0) {
                smerge[row * 8 + wn * 2]     = k1;
                smerge[row * 8 + wn * 2 + 1] = k2;
            }
        }
    }
    __syncthreads();
    if (tid < 128 && (m0 + tid) < nTok) {
        unsigned long long k1 = 0xFFFFFFFFFFFFFFFFULL, k2 = k1;
#pragma unroll
        for (int j = 0; j < 8; j++) {
            unsigned long long k = smerge[tid * 8 + j];
            if (k < k1) { k2 = k1; k1 = k; }
            else if (k < k2) { k2 = k; }
        }
        unsigned* dst = g_cand + (size_t)(m0 + tid) * 64 + blockIdx.y * 2;
        dst[0] = (unsigned)(k1 & 0xffffffffu);
        dst[1] = (unsigned)(k2 & 0xffffffffu);
    }
}

// ---------------- exact fp32 rescore of 64 candidates/token ----------------
__global__ void k_rescore(const float* __restrict__ embed, int nTok) {
    int tok = blockIdx.x * 8 + (threadIdx.x >> 5);
    int lane = threadIdx.x & 31;
    if (tok >= nTok) return;
    float z[16];
#pragma unroll
    for (int j = 0; j < 16; j++) {
        int a = tok * ND + lane + 32 * j;
        z[j] = __half2float(g_zH[a]) + __half2float(g_zL[a]);
    }
    float best = 3.4e38f; int bidx = 0x7fffffff;
    const unsigned* cand = g_cand + (size_t)tok * 64;
    for (int c = 0; c < 64; c++) {
        int idx = (int)cand[c];
        const float* e = embed + (size_t)idx * ND;
        float dot = 0.f;
#pragma unroll
        for (int j = 0; j < 16; j++)
            dot = fmaf(z[j], __ldg(e + lane + 32 * j), dot);
#pragma unroll
        for (int o = 16; o > 0; o >>= 1)
            dot += __shfl_xor_sync(0xffffffffu, dot, o);
        float sc = fmaf(-2.f, dot, g_esq[idx]);
        if (sc < best || (sc == best && idx < bidx)) { best = sc; bidx = idx; }
    }
    if (lane == 0) g_keys[tok] = (unsigned long long)(unsigned)bidx;
}

// ---------------- fused epilogue: gather tapw + interp + Phi mix + resid ------
// outp != null: also emits out = x - new_resid (si==9).
// rn == 1: also writes split(new_resid) to z (next scale s=512, identity down)
// rn == 2: also writes pair-mean split to z (next scale s=256, r=2 down)
__global__ void k_phi_ep(const float* __restrict__ embed,
                         const float* __restrict__ bias,
                         int s, int p, const float* __restrict__ rsrc,
                         const float* __restrict__ xp, float* __restrict__ outp,
                         int rn) {
    __shared__ float4 s_ex[256];
    int total = NB * NL * 128;
    float ratio = (float)s * (1.0f / 512.0f);
    for (int t = blockIdx.x * blockDim.x + threadIdx.x; t < total;
         t += gridDim.x * blockDim.x) {
        int d4 = t & 127;
        int bl = t >> 7;
        int b = bl >> 9, l = bl & 511;
        const unsigned long long* kb = g_keys + b * s;
        float4 sum = *(const float4*)(bias + (d4 << 2));
        float4 qup = make_float4(0.f, 0.f, 0.f, 0.f);
#pragma unroll
        for (int k = 0; k < 3; k++) {
            int lp = l + k - 1;
            if ((unsigned)lp < 512u) {
                float pos = ((float)lp + 0.5f) * ratio - 0.5f;
                float fl = floorf(pos);
                int i0 = (int)fl;
                float f = pos - fl;
                int ia, ib;
                if (i0 < 0)          { ia = 0;     ib = 0;     f = 0.f; }
                else if (i0 >= s - 1){ ia = s - 1; ib = s - 1; f = 0.f; }
                else                 { ia = i0;    ib = i0 + 1; }
                float w1 = 1.0f - f, w2 = f;
                int ca = (int)(unsigned)(kb[ia] & 0xffffffffULL);
                const float* base = g_tapw + (size_t)(p * 3 + k) * (NCB * ND);
                float4 va = *((const float4*)(base + ((size_t)ca << 9)) + d4);
                sum.x += w1 * va.x; sum.y += w1 * va.y;
                sum.z += w1 * va.z; sum.w += w1 * va.w;
                if (k == 1) {
                    float4 ea = *((const float4*)(embed + ((size_t)ca << 9)) + d4);
                    qup.x = w1 * ea.x; qup.y = w1 * ea.y;
                    qup.z = w1 * ea.z; qup.w = w1 * ea.w;
                }
                if (w2 > 0.f) {
                    int cb = (int)(unsigned)(kb[ib] & 0xffffffffULL);
                    float4 vb = *((const float4*)(base + ((size_t)cb << 9)) + d4);
                    sum.x += w2 * vb.x; sum.y += w2 * vb.y;
                    sum.z += w2 * vb.z; sum.w += w2 * vb.w;
                    if (k == 1) {
                        float4 eb = *((const float4*)(embed + ((size_t)cb << 9)) + d4);
                        qup.x += w2 * eb.x; qup.y += w2 * eb.y;
                        qup.z += w2 * eb.z; qup.w += w2 * eb.w;
                    }
                }
            }
        }
        int adr = (bl << 9) + (d4 << 2);
        float4 rs = *(const float4*)(rsrc + adr);
        rs.x -= 0.5f * qup.x + 0.5f * sum.x;
        rs.y -= 0.5f * qup.y + 0.5f * sum.y;
        rs.z -= 0.5f * qup.z + 0.5f * sum.z;
        rs.w -= 0.5f * qup.w + 0.5f * sum.w;
        *(float4*)(g_resid + adr) = rs;
        if (outp) {
            float4 xv = *(const float4*)(xp + adr);
            *(float4*)(outp + adr) =
                make_float4(xv.x - rs.x, xv.y - rs.y, xv.z - rs.z, xv.w - rs.w);
        }
        if (rn == 1) {
            // next scale s=512: z = resid (identity downsample), split
            split_h(rs.x, g_zH[adr + 0], g_zL[adr + 0]);
            split_h(rs.y, g_zH[adr + 1], g_zL[adr + 1]);
            split_h(rs.z, g_zH[adr + 2], g_zL[adr + 2]);
            split_h(rs.w, g_zH[adr + 3], g_zL[adr + 3]);
        } else if (rn == 2) {
            // next scale s=256: pair-mean over (even l, odd l) held by this CTA
            int tid = threadIdx.x;
            s_ex[tid] = rs;
            __syncthreads();
            if (tid < 128) {   // even-l half (bl = 2*blockIdx.x)
                float4 o = s_ex[tid + 128];
                float4 m = make_float4((rs.x + o.x) * 0.5f, (rs.y + o.y) * 0.5f,
                                       (rs.z + o.z) * 0.5f, (rs.w + o.w) * 0.5f);
                int bt = (b << 8) + (l >> 1);         // b*256 + l/2
                int zi = (bt << 9) + (d4 << 2);
                split_h(m.x, g_zH[zi + 0], g_zL[zi + 0]);
                split_h(m.y, g_zH[zi + 1], g_zL[zi + 1]);
                split_h(m.z, g_zH[zi + 2], g_zL[zi + 2]);
                split_h(m.w, g_zH[zi + 3], g_zL[zi + 3]);
            }
            __syncthreads();
        }
    }
}

// ---------------- host ----------------
extern "C" void kernel_launch(void* const* d_in, const int* in_sizes, int n_in,
                              void* d_out, int out_size) {
    const float* x     = (const float*)d_in[0];
    const float* embed = (const float*)d_in[1];
    const float* phi_w = (const float*)d_in[2];
    const float* phi_b = (const float*)d_in[3];
    float* out = (float*)d_out;

    float* residPtr = nullptr;
    cudaGetSymbolAddress((void**)&residPtr, g_resid);

    // Side stream (high priority) + events. Created once on the first,
    // non-captured correctness call; reused during graph capture.
    static cudaStream_t s2 = nullptr;
    static cudaEvent_t evA = nullptr, evB = nullptr,
                       evP[4] = {nullptr, nullptr, nullptr, nullptr};
    if (!s2) {
        int loPri = 0, hiPri = 0;
        cudaDeviceGetStreamPriorityRange(&loPri, &hiPri);
        cudaStreamCreateWithPriority(&s2, cudaStreamNonBlocking, hiPri);
        cudaEventCreateWithFlags(&evA, cudaEventDisableTiming);
        cudaEventCreateWithFlags(&evB, cudaEventDisableTiming);
        for (int p = 0; p < 4; p++)
            cudaEventCreateWithFlags(&evP[p], cudaEventDisableTiming);
        cudaFuncSetAttribute(k_gemm_pre,
                             cudaFuncAttributeMaxDynamicSharedMemorySize, 2 * STAGE3_B);
        cudaFuncSetAttribute(k_quant1,
                             cudaFuncAttributeMaxDynamicSharedMemorySize, 2 * STAGE1_B);
    }

    // Replicate np.linspace(1/12, 11/12, 4) + first-min tie-break in double.
    double start = 1.0 / 3.0 / 4.0;
    double stop  = 1.0 - 1.0 / 3.0 / 4.0;
    double step  = (stop - start) / 3.0;
    double ticks[4] = { start, start + step, start + 2.0 * step, stop };
    int scales[10] = { 1, 2, 4, 8, 16, 32, 64, 128, 256, 512 };
    int phi_idx[10];
    for (int si = 0; si < 10; si++) {
        double v = (double)si / 9.0;
        int bk = 0; double bd = fabs(ticks[0] - v);
        for (int k = 1; k < 4; k++) {
            double dd = fabs(ticks[k] - v);
            if (dd < bd) { bd = dd; bk = k; }
        }
        phi_idx[si] = bk;
    }
    int first_use[4] = { -1, -1, -1, -1 };
    for (int si = 0; si < 10; si++)
        if (first_use[phi_idx[si]] < 0) first_use[phi_idx[si]] = si;

    // setup: get pre(p0) started as early as possible
    k_split_emb<<<1024, 256>>>(embed);
    k_setup_wt<<<512, 256>>>(phi_w, 0);
    cudaEventRecord(evA, 0);
    cudaStreamWaitEvent(s2, evA, 0);
    k_gemm_pre<<<dim3(32, 4, 3), 256, 2 * STAGE3_B, s2>>>(0);
    cudaEventRecord(evP[0], s2);

    k_setup_wt<<<512, 256>>>(phi_w, 1);
    k_setup_wt<<<512, 256>>>(phi_w, 2);
    k_setup_wt<<<512, 256>>>(phi_w, 3);
    cudaEventRecord(evB, 0);
    cudaStreamWaitEvent(s2, evB, 0);
    for (int p = 1; p < 4; p++) {
        k_gemm_pre<<<dim3(32, 4, 3), 256, 2 * STAGE3_B, s2>>>(p);
        cudaEventRecord(evP[p], s2);
    }
    k_setup_esq<<<512, 256>>>(embed);

    for (int si = 0; si < 10; si++) {
        int s = scales[si];
        int nTok = NB * s;
        const float* src = (si == 0) ? x : residPtr;
        int p = phi_idx[si];

        // z for si==8 / si==9 is produced by the previous phi_ep (fused down)
        if (si < 8) {
            if (s <= 16) {
                int segs = (NL / s) / 16;
                int t1 = NB * s * segs * 128;
                int b1 = (t1 + 255) / 256; if (b1 > 2048) b1 = 2048;
                k_down1<<<b1, 256>>>(s, segs, src);
                int t2 = NB * s * 128;
                int b2 = (t2 + 255) / 256;
                k_down2<<<b2, 256>>>(s, segs);
            } else {
                int total = NB * s * ND;
                int blk = (total + 255) / 256; if (blk > 8192) blk = 8192;
                k_down<<<blk, 256>>>(s, src);
            }
        }

        int mTiles = (nTok + 127) / 128;
        k_quant1<<<dim3(mTiles, NCB / 128), 256, 2 * STAGE1_B>>>(nTok);
        k_rescore<<<(nTok + 7) / 8, 256>>>(embed, nTok);

        if (si == first_use[p])
            cudaStreamWaitEvent(0, evP[p], 0);

        bool last = (si == 9);
        int rn = (si == 7) ? 2 : (si == 8) ? 1 : 0;
        k_phi_ep<<<4096, 256>>>(embed, phi_b + p * ND, s, p, src,
                                last ? x : (const float*)nullptr,
                                last ? out : (float*)nullptr, rn);
    }
}